// round 7
// baseline (speedup 1.0000x reference)
#include <cuda_runtime.h>
#include <cuda_bf16.h>
#include <cstdint>

// Problem constants
#define NPTS      65536
#define DIM       64
#define NCODE     1024
#define HW        4096
#define CHW       262144
#define TOTAL_Q   4194304

// Output layout (concatenated, reference return order, float32)
#define OFF_Q     0
#define OFF_LOSS  4194304
#define OFF_IDX   4194305
#define OFF_EMB   4259841
#define OFF_CS    4325377
#define OFF_EA    4326401

// Scratch
__device__ float g_dw[DIM * NCODE];
__device__ float g_enc[NCODE];
__device__ float g_e2[NCODE];
__device__ float g_loss;
__device__ float g_nsum;
__device__ int   g_nflag;
__device__ int   g_flagged[NPTS];

// ---------------- smem layout (bytes) ----------------
// A/B tiles: 128 rows x 272 bytes (64 bf16 hi @0, 64 bf16 lo @128, 16B pad)
#define ROWB     272
#define SM_A     0
#define SM_B     34816
#define SM_E2    69632          // 128 floats
#define SM_V1    70144          // 256 floats
#define SM_V2    71168          // 256 floats
#define SM_I1    72192          // 256 ints
#define SM_RUNV  73216          // 128 floats
#define SM_RUNV2 73728          // 128 floats
#define SM_RUNI  74240          // 128 ints
#define SM_RED   74752          // 256 floats
#define SM_TOTAL 75776

__device__ __forceinline__ uint32_t smem_u32(const void* p) {
    uint32_t a;
    asm("{ .reg .u64 t; cvta.to.shared.u64 t, %1; cvt.u32.u64 %0, t; }" : "=r"(a) : "l"(p));
    return a;
}

#define LDSM4(r, a) \
    asm volatile("ldmatrix.sync.aligned.m8n8.x4.shared.b16 {%0,%1,%2,%3}, [%4];" \
        : "=r"((r)[0]), "=r"((r)[1]), "=r"((r)[2]), "=r"((r)[3]) : "r"(a))

#define MMA_BF16(d, a, b0, b1) \
    asm volatile("mma.sync.aligned.m16n8k16.row.col.f32.bf16.bf16.f32 " \
        "{%0,%1,%2,%3}, {%4,%5,%6,%7}, {%8,%9}, {%0,%1,%2,%3};" \
        : "+f"((d)[0]), "+f"((d)[1]), "+f"((d)[2]), "+f"((d)[3]) \
        : "r"((a)[0]), "r"((a)[1]), "r"((a)[2]), "r"((a)[3]), "r"(b0), "r"(b1))

__device__ __forceinline__ uint32_t pack_hilo(float v0, float v1, uint32_t& lo_pack) {
    __nv_bfloat16 h0 = __float2bfloat16(v0);
    __nv_bfloat16 h1 = __float2bfloat16(v1);
    __nv_bfloat16 l0 = __float2bfloat16(v0 - __bfloat162float(h0));
    __nv_bfloat16 l1 = __float2bfloat16(v1 - __bfloat162float(h1));
    uint32_t hp = ((uint32_t)__bfloat16_as_ushort(h1) << 16) | __bfloat16_as_ushort(h0);
    lo_pack    = ((uint32_t)__bfloat16_as_ushort(l1) << 16) | __bfloat16_as_ushort(l0);
    return hp;
}
__device__ __forceinline__ uint32_t pack_hi(float v0, float v1) {
    __nv_bfloat16 h0 = __float2bfloat16(v0);
    __nv_bfloat16 h1 = __float2bfloat16(v1);
    return ((uint32_t)__bfloat16_as_ushort(h1) << 16) | __bfloat16_as_ushort(h0);
}

// ---------------------------------------------------------------------------
// Kernel 1: init scratch + e2
// ---------------------------------------------------------------------------
__global__ void vq_init(const float* __restrict__ E) {
    int i = blockIdx.x * blockDim.x + threadIdx.x;
    if (i < DIM * NCODE) g_dw[i] = 0.0f;
    if (i < NCODE) {
        g_enc[i] = 0.0f;
        float s = 0.0f;
#pragma unroll
        for (int d = 0; d < DIM; ++d) {
            float v = E[d * NCODE + i];
            s = fmaf(v, v, s);
        }
        g_e2[i] = s;
    }
    if (i == 0) { g_loss = 0.0f; g_nflag = 0; }
}

// ---------------------------------------------------------------------------
// Kernel 2: bf16 mma.sync distance GEMM (2-pass: hi*hi + hi*lo) + argmin
// 256 threads = 8 warps (4 M x 2 N), 128 points/CTA, 8 chunks of 128 codes.
// ---------------------------------------------------------------------------
__global__ void __launch_bounds__(256, 1)
vq_main(const float* __restrict__ x, const float* __restrict__ E,
        float* __restrict__ out) {
    extern __shared__ char sm[];
    const uint32_t sb = smem_u32(sm);
    float* e2s  = (float*)(sm + SM_E2);
    float* v1s  = (float*)(sm + SM_V1);
    float* v2s  = (float*)(sm + SM_V2);
    int*   i1s  = (int*)(sm + SM_I1);
    float* runv = (float*)(sm + SM_RUNV);
    float* runv2= (float*)(sm + SM_RUNV2);
    int*   runi = (int*)(sm + SM_RUNI);
    float* red  = (float*)(sm + SM_RED);

    const int tid  = threadIdx.x;
    const int wid  = tid >> 5;
    const int lane = tid & 31;
    const int n0   = blockIdx.x * 128;
    const int bimg = n0 >> 12;
    const int p0   = n0 & 4095;
    const float* xb = x + (size_t)bimg * CHW + p0;

    // ---- pack A tile (hi only): rows = points m ----
#pragma unroll
    for (int it = 0; it < 16; ++it) {
        int g  = tid + 256 * it;
        int c2 = g >> 7;
        int m  = g & 127;
        float v0 = -2.0f * xb[(2 * c2) * HW + m];
        float v1 = -2.0f * xb[(2 * c2 + 1) * HW + m];
        *(uint32_t*)(sm + SM_A + m * ROWB + c2 * 4) = pack_hi(v0, v1);
    }
    if (tid < 128) {
        runv[tid] = 3.4e38f; runv2[tid] = 3.4e38f; runi[tid] = 0;
    }

    const int wm  = wid >> 1;
    const int wn  = wid & 1;
    const int m0  = wm * 32;
    const int nb0 = wn * 64;
    const int mrow  = (lane & 7) + ((lane >> 3) & 1) * 8;
    const int kcolB = ((lane >> 4) & 1) * 16;
    const uint32_t aBase = sb + SM_A + (m0 + mrow) * ROWB + kcolB;
    const uint32_t bBase = sb + SM_B + (nb0 + mrow) * ROWB + kcolB;

    for (int chunk = 0; chunk < 8; ++chunk) {
        __syncthreads();
        // ---- pack B (E chunk): hi + lo ----
#pragma unroll
        for (int it = 0; it < 16; ++it) {
            int g  = tid + 256 * it;
            int c2 = g >> 7;
            int j  = g & 127;
            float v0 = E[(2 * c2) * NCODE + chunk * 128 + j];
            float v1 = E[(2 * c2 + 1) * NCODE + chunk * 128 + j];
            uint32_t lp, hp = pack_hilo(v0, v1, lp);
            *(uint32_t*)(sm + SM_B + j * ROWB + c2 * 4)       = hp;
            *(uint32_t*)(sm + SM_B + j * ROWB + 128 + c2 * 4) = lp;
        }
        if (tid < 128) e2s[tid] = g_e2[chunk * 128 + tid];
        __syncthreads();

        uint32_t Ahi[2][4][4];
#pragma unroll
        for (int mt = 0; mt < 2; ++mt)
#pragma unroll
            for (int kb = 0; kb < 4; ++kb)
                LDSM4(Ahi[mt][kb], aBase + mt * (16 * ROWB) + kb * 32);

        float acc[2][8][4];
#pragma unroll
        for (int mt = 0; mt < 2; ++mt)
#pragma unroll
            for (int j = 0; j < 8; ++j)
#pragma unroll
                for (int c = 0; c < 4; ++c) acc[mt][j][c] = 0.0f;

#pragma unroll
        for (int kb = 0; kb < 4; ++kb) {
#pragma unroll
            for (int nt = 0; nt < 4; ++nt) {
                uint32_t Bh[4];
                LDSM4(Bh, bBase + nt * (16 * ROWB) + kb * 32);
#pragma unroll
                for (int mt = 0; mt < 2; ++mt)
#pragma unroll
                    for (int h = 0; h < 2; ++h)
                        MMA_BF16(acc[mt][nt * 2 + h], Ahi[mt][kb], Bh[h], Bh[h + 2]);
            }
#pragma unroll
            for (int nt = 0; nt < 4; ++nt) {
                uint32_t Bl[4];
                LDSM4(Bl, bBase + nt * (16 * ROWB) + kb * 32 + 128);
#pragma unroll
                for (int mt = 0; mt < 2; ++mt)
#pragma unroll
                    for (int h = 0; h < 2; ++h)
                        MMA_BF16(acc[mt][nt * 2 + h], Ahi[mt][kb], Bl[h], Bl[h + 2]);
            }
        }

        // ---- extraction ----
#pragma unroll
        for (int mt = 0; mt < 2; ++mt)
#pragma unroll
            for (int rr = 0; rr < 2; ++rr) {
                float b1v = 3.4e38f, b2v = 3.4e38f;
                int biI = 0;
#pragma unroll
                for (int j = 0; j < 8; ++j) {
                    int nA = nb0 + (j >> 1) * 16 + (j & 1) * 8 + (lane & 3) * 2;
                    float sc0 = acc[mt][j][rr * 2 + 0] + e2s[nA];
                    float sc1 = acc[mt][j][rr * 2 + 1] + e2s[nA + 1];
                    if (sc0 < b1v) { b2v = b1v; b1v = sc0; biI = chunk * 128 + nA; }
                    else if (sc0 < b2v) b2v = sc0;
                    if (sc1 < b1v) { b2v = b1v; b1v = sc1; biI = chunk * 128 + nA + 1; }
                    else if (sc1 < b2v) b2v = sc1;
                }
#pragma unroll
                for (int off = 1; off <= 2; off <<= 1) {
                    float o1 = __shfl_xor_sync(0xffffffffu, b1v, off);
                    float o2 = __shfl_xor_sync(0xffffffffu, b2v, off);
                    int   oi = __shfl_xor_sync(0xffffffffu, biI, off);
                    float nb2 = fminf(fminf(b2v, o2), fmaxf(b1v, o1));
                    if (o1 < b1v || (o1 == b1v && oi < biI)) { b1v = o1; biI = oi; }
                    b2v = nb2;
                }
                if ((lane & 3) == 0) {
                    int row = m0 + mt * 16 + (lane >> 2) + rr * 8;
                    v1s[row * 2 + wn] = b1v;
                    v2s[row * 2 + wn] = b2v;
                    i1s[row * 2 + wn] = biI;
                }
            }
        __syncthreads();

        if (tid < 128) {
            float a1 = v1s[tid * 2], a2 = v2s[tid * 2]; int ai = i1s[tid * 2];
            float c1 = v1s[tid * 2 + 1], c2v = v2s[tid * 2 + 1]; int ci = i1s[tid * 2 + 1];
            float m2 = fminf(fminf(a2, c2v), fmaxf(a1, c1));
            float m1; int mi;
            if (c1 < a1) { m1 = c1; mi = ci; } else { m1 = a1; mi = ai; }
            float r1 = runv[tid], r2 = runv2[tid];
            float nn2 = fminf(fminf(m2, r2), fmaxf(m1, r1));
            if (m1 < r1) { runv[tid] = m1; runi[tid] = mi; }
            runv2[tid] = nn2;
        }
    }
    __syncthreads();

    // ---- final epilogue ----
    if (tid < 128) {
        int k = runi[tid];
        out[OFF_IDX + n0 + tid] = (float)k;
        atomicAdd(&g_enc[k], 1.0f);
        if (runv2[tid] - runv[tid] < 0.2f) {
            int fp = atomicAdd(&g_nflag, 1);
            g_flagged[fp] = n0 + tid;
        }
    }
    __syncthreads();

    float lsum = 0.0f;
    float* outq = out + OFF_Q + (size_t)bimg * CHW + p0;
#pragma unroll 4
    for (int r = 0; r < 32; ++r) {
        int e = tid + 256 * r;
        int c = e >> 7;
        int m = e & 127;
        int k = runi[m];
        float xv = xb[c * HW + m];
        float ev = E[c * NCODE + k];
        float diff = ev - xv;
        outq[c * HW + m] = xv + diff;
        lsum = fmaf(diff, diff, lsum);
        atomicAdd(&g_dw[c * NCODE + k], xv);
    }

    red[tid] = lsum;
    __syncthreads();
    for (int s = 128; s > 0; s >>= 1) {
        if (tid < s) red[tid] += red[tid + s];
        __syncthreads();
    }
    if (tid == 0) atomicAdd(&g_loss, red[0]);
}

// ---------------------------------------------------------------------------
// Kernel 3: exact-fp32 rescue, one warp per flagged point
// ---------------------------------------------------------------------------
__global__ void __launch_bounds__(256)
vq_rescue(const float* __restrict__ x, const float* __restrict__ E,
          float* __restrict__ out) {
    __shared__ float xs[8][64];
    const int tid = threadIdx.x;
    const int wslot = tid >> 5;
    const int lane = tid & 31;
    const int gw = blockIdx.x * 8 + wslot;
    const int nw = gridDim.x * 8;
    const int nf = g_nflag;

    for (int it = gw; it < nf; it += nw) {
        int p = g_flagged[it];
        int bimg = p >> 12;
        int off = p & 4095;
        const float* xp = x + (size_t)bimg * CHW + off;
        xs[wslot][lane]      = xp[lane * HW];
        xs[wslot][lane + 32] = xp[(lane + 32) * HW];
        __syncwarp();

        float best = 3.4e38f; int kb = 0;
        for (int k0 = 0; k0 < NCODE; k0 += 32) {
            int k = k0 + lane;
            float dot = 0.0f;
#pragma unroll
            for (int c = 0; c < 64; ++c) dot = fmaf(xs[wslot][c], E[c * NCODE + k], dot);
            float sc = fmaf(-2.0f, dot, g_e2[k]);
            if (sc < best) { best = sc; kb = k; }
        }
#pragma unroll
        for (int offs = 16; offs > 0; offs >>= 1) {
            float ov = __shfl_xor_sync(0xffffffffu, best, offs);
            int   oi = __shfl_xor_sync(0xffffffffu, kb, offs);
            if (ov < best || (ov == best && oi < kb)) { best = ov; kb = oi; }
        }
        int kn = kb;
        int ko = (int)out[OFF_IDX + p];
        if (kn != ko) {
            if (lane == 0) {
                out[OFF_IDX + p] = (float)kn;
                atomicAdd(&g_enc[ko], -1.0f);
                atomicAdd(&g_enc[kn], 1.0f);
            }
            float ld = 0.0f;
#pragma unroll
            for (int h = 0; h < 2; ++h) {
                int c = lane + 32 * h;
                float xv = xs[wslot][c];
                atomicAdd(&g_dw[c * NCODE + ko], -xv);
                atomicAdd(&g_dw[c * NCODE + kn], xv);
                float eo = E[c * NCODE + ko];
                float en = E[c * NCODE + kn];
                float dold = eo - xv, dnew = en - xv;
                out[OFF_Q + (size_t)bimg * CHW + c * HW + off] = xv + dnew;
                ld += dnew * dnew - dold * dold;
            }
#pragma unroll
            for (int offs = 16; offs > 0; offs >>= 1)
                ld += __shfl_xor_sync(0xffffffffu, ld, offs);
            if (lane == 0) atomicAdd(&g_loss, ld);
        }
        __syncwarp();
    }
}

// ---------------------------------------------------------------------------
// Kernel 4a: cluster-size EMA + global sum (single block)
// ---------------------------------------------------------------------------
__global__ void vq_fin1(const float* __restrict__ cs_in, float* __restrict__ out) {
    __shared__ float red[1024];
    int k = threadIdx.x;
    float ncs = cs_in[k] * 0.99f + 0.01f * g_enc[k];
    out[OFF_CS + k] = ncs;
    red[k] = ncs;
    __syncthreads();
    for (int s = 512; s > 0; s >>= 1) {
        if (k < s) red[k] += red[k + s];
        __syncthreads();
    }
    if (k == 0) {
        g_nsum = red[0];
        out[OFF_LOSS] = 0.25f * g_loss * (1.0f / (float)TOTAL_Q);
    }
}

// ---------------------------------------------------------------------------
// Kernel 4b: embedding EMA + normalize (parallel over 64K elements)
// ---------------------------------------------------------------------------
__global__ void vq_fin2(const float* __restrict__ ea_in, float* __restrict__ out) {
    int idx = blockIdx.x * blockDim.x + threadIdx.x;
    if (idx >= DIM * NCODE) return;
    int k = idx & (NCODE - 1);
    float n = g_nsum;
    float ncs = out[OFF_CS + k];
    float cs = (ncs + 1e-5f) / (n + 1024.0f * 1e-5f) * n;
    float nea = ea_in[idx] * 0.99f + 0.01f * g_dw[idx];
    out[OFF_EA + idx] = nea;
    out[OFF_EMB + idx] = nea / cs;
}

// ---------------------------------------------------------------------------
extern "C" void kernel_launch(void* const* d_in, const int* in_sizes, int n_in,
                              void* d_out, int out_size) {
    const float* x  = (const float*)d_in[0];
    const float* E  = (const float*)d_in[1];
    const float* cs = (const float*)d_in[2];
    const float* ea = (const float*)d_in[3];
    float* out = (float*)d_out;

    cudaFuncSetAttribute(vq_main, cudaFuncAttributeMaxDynamicSharedMemorySize, SM_TOTAL);

    vq_init<<<256, 256>>>(E);
    vq_main<<<NPTS / 128, 256, SM_TOTAL>>>(x, E, out);
    vq_rescue<<<256, 256>>>(x, E, out);
    vq_fin1<<<1, 1024>>>(cs, out);
    vq_fin2<<<256, 256>>>(ea, out);
}

// round 8
// speedup vs baseline: 1.2583x; 1.2583x over previous
#include <cuda_runtime.h>
#include <cuda_bf16.h>
#include <cstdint>

// Problem constants
#define NPTS      65536
#define DIM       64
#define NCODE     1024
#define HW        4096
#define CHW       262144
#define TOTAL_Q   4194304

// Output layout (concatenated, reference return order, float32)
#define OFF_Q     0
#define OFF_LOSS  4194304
#define OFF_IDX   4194305
#define OFF_EMB   4259841
#define OFF_CS    4325377
#define OFF_EA    4326401

// Scratch
__device__ float g_dw[DIM * NCODE];
__device__ float g_enc[NCODE];
__device__ float g_e2[NCODE];
__device__ float g_loss;
__device__ float g_nsum;
__device__ int   g_nflag;
__device__ int   g_flagged[NPTS];

// ---------------- smem layout (bytes) ----------------
// A/B tiles: 128 rows x 272 bytes (64 bf16 hi @0, 64 bf16 lo @128, 16B pad)
#define ROWB     272
#define SM_A     0
#define SM_B     34816
#define SM_E2    69632          // 128 floats
#define SM_V1    70144          // 256 floats
#define SM_V2    71168          // 256 floats
#define SM_I1    72192          // 256 ints
#define SM_RUNV  73216          // 128 floats
#define SM_RUNV2 73728          // 128 floats
#define SM_RUNI  74240          // 128 ints
#define SM_RED   74752          // 256 floats
#define SM_TOTAL 75776

__device__ __forceinline__ uint32_t smem_u32(const void* p) {
    uint32_t a;
    asm("{ .reg .u64 t; cvta.to.shared.u64 t, %1; cvt.u32.u64 %0, t; }" : "=r"(a) : "l"(p));
    return a;
}

#define LDSM4(r, a) \
    asm volatile("ldmatrix.sync.aligned.m8n8.x4.shared.b16 {%0,%1,%2,%3}, [%4];" \
        : "=r"((r)[0]), "=r"((r)[1]), "=r"((r)[2]), "=r"((r)[3]) : "r"(a))

#define MMA_BF16(d, a, b0, b1) \
    asm volatile("mma.sync.aligned.m16n8k16.row.col.f32.bf16.bf16.f32 " \
        "{%0,%1,%2,%3}, {%4,%5,%6,%7}, {%8,%9}, {%0,%1,%2,%3};" \
        : "+f"((d)[0]), "+f"((d)[1]), "+f"((d)[2]), "+f"((d)[3]) \
        : "r"((a)[0]), "r"((a)[1]), "r"((a)[2]), "r"((a)[3]), "r"(b0), "r"(b1))

__device__ __forceinline__ uint32_t pack_hilo(float v0, float v1, uint32_t& lo_pack) {
    __nv_bfloat16 h0 = __float2bfloat16(v0);
    __nv_bfloat16 h1 = __float2bfloat16(v1);
    __nv_bfloat16 l0 = __float2bfloat16(v0 - __bfloat162float(h0));
    __nv_bfloat16 l1 = __float2bfloat16(v1 - __bfloat162float(h1));
    uint32_t hp = ((uint32_t)__bfloat16_as_ushort(h1) << 16) | __bfloat16_as_ushort(h0);
    lo_pack    = ((uint32_t)__bfloat16_as_ushort(l1) << 16) | __bfloat16_as_ushort(l0);
    return hp;
}

// ---------------------------------------------------------------------------
// Kernel 1: init scratch + e2
// ---------------------------------------------------------------------------
__global__ void vq_init(const float* __restrict__ E) {
    int i = blockIdx.x * blockDim.x + threadIdx.x;
    if (i < DIM * NCODE) g_dw[i] = 0.0f;
    if (i < NCODE) {
        g_enc[i] = 0.0f;
        float s = 0.0f;
#pragma unroll
        for (int d = 0; d < DIM; ++d) {
            float v = E[d * NCODE + i];
            s = fmaf(v, v, s);
        }
        g_e2[i] = s;
    }
    if (i == 0) { g_loss = 0.0f; g_nflag = 0; }
}

// ---------------------------------------------------------------------------
// Kernel 2: bf16 mma.sync distance GEMM (3-pass compensated) + argmin
// 256 threads = 8 warps (4 M x 2 N), 128 points/CTA, 8 chunks of 128 codes.
// ---------------------------------------------------------------------------
__global__ void __launch_bounds__(256, 1)
vq_main(const float* __restrict__ x, const float* __restrict__ E,
        float* __restrict__ out) {
    extern __shared__ char sm[];
    const uint32_t sb = smem_u32(sm);
    float* e2s  = (float*)(sm + SM_E2);
    float* v1s  = (float*)(sm + SM_V1);
    float* v2s  = (float*)(sm + SM_V2);
    int*   i1s  = (int*)(sm + SM_I1);
    float* runv = (float*)(sm + SM_RUNV);
    float* runv2= (float*)(sm + SM_RUNV2);
    int*   runi = (int*)(sm + SM_RUNI);
    float* red  = (float*)(sm + SM_RED);

    const int tid  = threadIdx.x;
    const int wid  = tid >> 5;
    const int lane = tid & 31;
    const int n0   = blockIdx.x * 128;
    const int bimg = n0 >> 12;
    const int p0   = n0 & 4095;
    const float* xb = x + (size_t)bimg * CHW + p0;

    // ---- pack A tile: rows = points m, cols = 64 hi | 64 lo bf16 ----
#pragma unroll
    for (int it = 0; it < 16; ++it) {
        int g  = tid + 256 * it;
        int c2 = g >> 7;
        int m  = g & 127;
        float v0 = -2.0f * xb[(2 * c2) * HW + m];
        float v1 = -2.0f * xb[(2 * c2 + 1) * HW + m];
        uint32_t lp, hp = pack_hilo(v0, v1, lp);
        *(uint32_t*)(sm + SM_A + m * ROWB + c2 * 4)       = hp;
        *(uint32_t*)(sm + SM_A + m * ROWB + 128 + c2 * 4) = lp;
    }
    if (tid < 128) {
        runv[tid] = 3.4e38f; runv2[tid] = 3.4e38f; runi[tid] = 0;
    }

    const int wm  = wid >> 1;
    const int wn  = wid & 1;
    const int m0  = wm * 32;
    const int nb0 = wn * 64;
    const int mrow  = (lane & 7) + ((lane >> 3) & 1) * 8;
    const int kcolB = ((lane >> 4) & 1) * 16;
    const uint32_t aBase = sb + SM_A + (m0 + mrow) * ROWB + kcolB;
    const uint32_t bBase = sb + SM_B + (nb0 + mrow) * ROWB + kcolB;

    for (int chunk = 0; chunk < 8; ++chunk) {
        __syncthreads();
        // ---- pack B (E chunk): hi + lo ----
#pragma unroll
        for (int it = 0; it < 16; ++it) {
            int g  = tid + 256 * it;
            int c2 = g >> 7;
            int j  = g & 127;
            float v0 = E[(2 * c2) * NCODE + chunk * 128 + j];
            float v1 = E[(2 * c2 + 1) * NCODE + chunk * 128 + j];
            uint32_t lp, hp = pack_hilo(v0, v1, lp);
            *(uint32_t*)(sm + SM_B + j * ROWB + c2 * 4)       = hp;
            *(uint32_t*)(sm + SM_B + j * ROWB + 128 + c2 * 4) = lp;
        }
        if (tid < 128) e2s[tid] = g_e2[chunk * 128 + tid];
        __syncthreads();

        // ---- load A fragments (hi + lo, held all chunk) ----
        uint32_t Ahi[2][4][4], Alo[2][4][4];
#pragma unroll
        for (int mt = 0; mt < 2; ++mt)
#pragma unroll
            for (int kb = 0; kb < 4; ++kb) {
                LDSM4(Ahi[mt][kb], aBase + mt * (16 * ROWB) + kb * 32);
                LDSM4(Alo[mt][kb], aBase + mt * (16 * ROWB) + kb * 32 + 128);
            }

        float acc[2][8][4];
#pragma unroll
        for (int mt = 0; mt < 2; ++mt)
#pragma unroll
            for (int j = 0; j < 8; ++j)
#pragma unroll
                for (int c = 0; c < 4; ++c) acc[mt][j][c] = 0.0f;

#pragma unroll
        for (int kb = 0; kb < 4; ++kb) {
#pragma unroll
            for (int nt = 0; nt < 4; ++nt) {
                uint32_t Bh[4];
                LDSM4(Bh, bBase + nt * (16 * ROWB) + kb * 32);
#pragma unroll
                for (int mt = 0; mt < 2; ++mt)
#pragma unroll
                    for (int h = 0; h < 2; ++h) {
                        MMA_BF16(acc[mt][nt * 2 + h], Ahi[mt][kb], Bh[h], Bh[h + 2]);
                        MMA_BF16(acc[mt][nt * 2 + h], Alo[mt][kb], Bh[h], Bh[h + 2]);
                    }
            }
#pragma unroll
            for (int nt = 0; nt < 4; ++nt) {
                uint32_t Bl[4];
                LDSM4(Bl, bBase + nt * (16 * ROWB) + kb * 32 + 128);
#pragma unroll
                for (int mt = 0; mt < 2; ++mt)
#pragma unroll
                    for (int h = 0; h < 2; ++h)
                        MMA_BF16(acc[mt][nt * 2 + h], Ahi[mt][kb], Bl[h], Bl[h + 2]);
            }
        }

        // ---- extraction ----
#pragma unroll
        for (int mt = 0; mt < 2; ++mt)
#pragma unroll
            for (int rr = 0; rr < 2; ++rr) {
                float b1v = 3.4e38f, b2v = 3.4e38f;
                int biI = 0;
#pragma unroll
                for (int j = 0; j < 8; ++j) {
                    int nA = nb0 + (j >> 1) * 16 + (j & 1) * 8 + (lane & 3) * 2;
                    float sc0 = acc[mt][j][rr * 2 + 0] + e2s[nA];
                    float sc1 = acc[mt][j][rr * 2 + 1] + e2s[nA + 1];
                    if (sc0 < b1v) { b2v = b1v; b1v = sc0; biI = chunk * 128 + nA; }
                    else if (sc0 < b2v) b2v = sc0;
                    if (sc1 < b1v) { b2v = b1v; b1v = sc1; biI = chunk * 128 + nA + 1; }
                    else if (sc1 < b2v) b2v = sc1;
                }
#pragma unroll
                for (int off = 1; off <= 2; off <<= 1) {
                    float o1 = __shfl_xor_sync(0xffffffffu, b1v, off);
                    float o2 = __shfl_xor_sync(0xffffffffu, b2v, off);
                    int   oi = __shfl_xor_sync(0xffffffffu, biI, off);
                    float nb2 = fminf(fminf(b2v, o2), fmaxf(b1v, o1));
                    if (o1 < b1v || (o1 == b1v && oi < biI)) { b1v = o1; biI = oi; }
                    b2v = nb2;
                }
                if ((lane & 3) == 0) {
                    int row = m0 + mt * 16 + (lane >> 2) + rr * 8;
                    v1s[row * 2 + wn] = b1v;
                    v2s[row * 2 + wn] = b2v;
                    i1s[row * 2 + wn] = biI;
                }
            }
        __syncthreads();

        if (tid < 128) {
            float a1 = v1s[tid * 2], a2 = v2s[tid * 2]; int ai = i1s[tid * 2];
            float c1 = v1s[tid * 2 + 1], c2v = v2s[tid * 2 + 1]; int ci = i1s[tid * 2 + 1];
            float m2 = fminf(fminf(a2, c2v), fmaxf(a1, c1));
            float m1; int mi;
            if (c1 < a1) { m1 = c1; mi = ci; } else { m1 = a1; mi = ai; }
            float r1 = runv[tid], r2 = runv2[tid];
            float nn2 = fminf(fminf(m2, r2), fmaxf(m1, r1));
            if (m1 < r1) { runv[tid] = m1; runi[tid] = mi; }
            runv2[tid] = nn2;
        }
    }
    __syncthreads();

    // ---- final epilogue ----
    if (tid < 128) {
        int k = runi[tid];
        out[OFF_IDX + n0 + tid] = (float)k;
        atomicAdd(&g_enc[k], 1.0f);
        if (runv2[tid] - runv[tid] < 4e-3f) {
            int fp = atomicAdd(&g_nflag, 1);
            g_flagged[fp] = n0 + tid;
        }
    }
    __syncthreads();

    float lsum = 0.0f;
    float* outq = out + OFF_Q + (size_t)bimg * CHW + p0;
#pragma unroll 4
    for (int r = 0; r < 32; ++r) {
        int e = tid + 256 * r;
        int c = e >> 7;
        int m = e & 127;
        int k = runi[m];
        float xv = xb[c * HW + m];
        float ev = E[c * NCODE + k];
        float diff = ev - xv;
        outq[c * HW + m] = xv + diff;
        lsum = fmaf(diff, diff, lsum);
        atomicAdd(&g_dw[c * NCODE + k], xv);
    }

    red[tid] = lsum;
    __syncthreads();
    for (int s = 128; s > 0; s >>= 1) {
        if (tid < s) red[tid] += red[tid + s];
        __syncthreads();
    }
    if (tid == 0) atomicAdd(&g_loss, red[0]);
}

// ---------------------------------------------------------------------------
// Kernel 3: exact-fp32 rescue, one warp per flagged point
// ---------------------------------------------------------------------------
__global__ void __launch_bounds__(256)
vq_rescue(const float* __restrict__ x, const float* __restrict__ E,
          float* __restrict__ out) {
    __shared__ float xs[8][64];
    const int tid = threadIdx.x;
    const int wslot = tid >> 5;
    const int lane = tid & 31;
    const int gw = blockIdx.x * 8 + wslot;
    const int nw = gridDim.x * 8;
    const int nf = g_nflag;

    for (int it = gw; it < nf; it += nw) {
        int p = g_flagged[it];
        int bimg = p >> 12;
        int off = p & 4095;
        const float* xp = x + (size_t)bimg * CHW + off;
        xs[wslot][lane]      = xp[lane * HW];
        xs[wslot][lane + 32] = xp[(lane + 32) * HW];
        __syncwarp();

        float best = 3.4e38f; int kb = 0;
        for (int k0 = 0; k0 < NCODE; k0 += 32) {
            int k = k0 + lane;
            float dot = 0.0f;
#pragma unroll
            for (int c = 0; c < 64; ++c) dot = fmaf(xs[wslot][c], E[c * NCODE + k], dot);
            float sc = fmaf(-2.0f, dot, g_e2[k]);
            if (sc < best) { best = sc; kb = k; }
        }
#pragma unroll
        for (int offs = 16; offs > 0; offs >>= 1) {
            float ov = __shfl_xor_sync(0xffffffffu, best, offs);
            int   oi = __shfl_xor_sync(0xffffffffu, kb, offs);
            if (ov < best || (ov == best && oi < kb)) { best = ov; kb = oi; }
        }
        int kn = kb;
        int ko = (int)out[OFF_IDX + p];
        if (kn != ko) {
            if (lane == 0) {
                out[OFF_IDX + p] = (float)kn;
                atomicAdd(&g_enc[ko], -1.0f);
                atomicAdd(&g_enc[kn], 1.0f);
            }
            float ld = 0.0f;
#pragma unroll
            for (int h = 0; h < 2; ++h) {
                int c = lane + 32 * h;
                float xv = xs[wslot][c];
                atomicAdd(&g_dw[c * NCODE + ko], -xv);
                atomicAdd(&g_dw[c * NCODE + kn], xv);
                float eo = E[c * NCODE + ko];
                float en = E[c * NCODE + kn];
                float dold = eo - xv, dnew = en - xv;
                out[OFF_Q + (size_t)bimg * CHW + c * HW + off] = xv + dnew;
                ld += dnew * dnew - dold * dold;
            }
#pragma unroll
            for (int offs = 16; offs > 0; offs >>= 1)
                ld += __shfl_xor_sync(0xffffffffu, ld, offs);
            if (lane == 0) atomicAdd(&g_loss, ld);
        }
        __syncwarp();
    }
}

// ---------------------------------------------------------------------------
// Kernel 4a: cluster-size EMA + global sum (single block)
// ---------------------------------------------------------------------------
__global__ void vq_fin1(const float* __restrict__ cs_in, float* __restrict__ out) {
    __shared__ float red[1024];
    int k = threadIdx.x;
    float ncs = cs_in[k] * 0.99f + 0.01f * g_enc[k];
    out[OFF_CS + k] = ncs;
    red[k] = ncs;
    __syncthreads();
    for (int s = 512; s > 0; s >>= 1) {
        if (k < s) red[k] += red[k + s];
        __syncthreads();
    }
    if (k == 0) {
        g_nsum = red[0];
        out[OFF_LOSS] = 0.25f * g_loss * (1.0f / (float)TOTAL_Q);
    }
}

// ---------------------------------------------------------------------------
// Kernel 4b: embedding EMA + normalize (parallel over 64K elements)
// ---------------------------------------------------------------------------
__global__ void vq_fin2(const float* __restrict__ ea_in, float* __restrict__ out) {
    int idx = blockIdx.x * blockDim.x + threadIdx.x;
    if (idx >= DIM * NCODE) return;
    int k = idx & (NCODE - 1);
    float n = g_nsum;
    float ncs = out[OFF_CS + k];
    float cs = (ncs + 1e-5f) / (n + 1024.0f * 1e-5f) * n;
    float nea = ea_in[idx] * 0.99f + 0.01f * g_dw[idx];
    out[OFF_EA + idx] = nea;
    out[OFF_EMB + idx] = nea / cs;
}

// ---------------------------------------------------------------------------
extern "C" void kernel_launch(void* const* d_in, const int* in_sizes, int n_in,
                              void* d_out, int out_size) {
    const float* x  = (const float*)d_in[0];
    const float* E  = (const float*)d_in[1];
    const float* cs = (const float*)d_in[2];
    const float* ea = (const float*)d_in[3];
    float* out = (float*)d_out;

    cudaFuncSetAttribute(vq_main, cudaFuncAttributeMaxDynamicSharedMemorySize, SM_TOTAL);

    vq_init<<<256, 256>>>(E);
    vq_main<<<NPTS / 128, 256, SM_TOTAL>>>(x, E, out);
    vq_rescue<<<256, 256>>>(x, E, out);
    vq_fin1<<<1, 1024>>>(cs, out);
    vq_fin2<<<256, 256>>>(ea, out);
}